// round 3
// baseline (speedup 1.0000x reference)
#include <cuda_runtime.h>
#include <cuda.h>
#include <cuda_bf16.h>
#include <cstdint>
#include <cstddef>

// ---------------- problem dims (fixed) ----------------
#define TT 8192
#define KK 4096
#define NN 4096

#define TILE_M 128
#define TILE_N 128
#define TILE_K 128                 // int8 bytes per chunk
#define NCHUNK (KK / TILE_K)       // 32
#define NSTAGE 3

// stage: A1 16K | A0 16K | B1 16K | B0 16K = 65536
#define STAGE_BYTES 65536
#define OFF_TILE 1024
#define SMEM_TOTAL (OFF_TILE + NSTAGE * STAGE_BYTES)   // 197632

#define QMAX 16256.0f              // 127*128

// ---------------- scratch (device globals; no allocation) --------------
__device__ int8_t g_x1[(size_t)TT * KK];
__device__ int8_t g_x0[(size_t)TT * KK];
__device__ int8_t g_w1[(size_t)NN * KK];
__device__ int8_t g_w0[(size_t)NN * KK];
__device__ float  g_sx[TT];
__device__ float  g_sw[NN];

// ---------------- PTX helpers (non-'a' baseline only) -------------------
__device__ __forceinline__ uint32_t smem_u32(const void* p) {
    uint32_t a;
    asm("{ .reg .u64 t; cvta.to.shared.u64 t, %1; cvt.u32.u64 %0, t; }"
        : "=r"(a) : "l"(p));
    return a;
}

__device__ __forceinline__ void mbar_init(uint32_t addr, uint32_t count) {
    asm volatile("mbarrier.init.shared.b64 [%0], %1;" :: "r"(addr), "r"(count) : "memory");
}

__device__ __forceinline__ void mbar_expect_tx(uint32_t addr, uint32_t bytes) {
    asm volatile("mbarrier.arrive.expect_tx.shared.b64 _, [%0], %1;"
                 :: "r"(addr), "r"(bytes) : "memory");
}

__device__ __forceinline__ void mbar_wait(uint32_t addr, uint32_t parity) {
    asm volatile(
        "{\n\t"
        ".reg .pred P;\n\t"
        "LAB_WAIT_%=:\n\t"
        "mbarrier.try_wait.parity.acquire.cta.shared::cta.b64 P, [%0], %1, 0x989680;\n\t"
        "@P bra LAB_DONE_%=;\n\t"
        "bra LAB_WAIT_%=;\n\t"
        "LAB_DONE_%=:\n\t"
        "}"
        :: "r"(addr), "r"(parity) : "memory");
}

__device__ __forceinline__ void tma_load3(uint32_t dst, const CUtensorMap* map,
                                          int cx, int cy, uint32_t mbar) {
    asm volatile(
        "cp.async.bulk.tensor.3d.shared::cta.global.tile.mbarrier::complete_tx::bytes "
        "[%0], [%1, {%2, %3, %4}], [%5];"
        :: "r"(dst), "l"(map), "r"(cx), "r"(cy), "r"(0), "r"(mbar)
        : "memory");
}

__device__ __forceinline__ void ldsm4(uint32_t* r, uint32_t addr) {
    asm volatile("ldmatrix.sync.aligned.m8n8.x4.shared.b16 {%0,%1,%2,%3}, [%4];"
                 : "=r"(r[0]), "=r"(r[1]), "=r"(r[2]), "=r"(r[3]) : "r"(addr));
}

__device__ __forceinline__ void mma_s8(int* c, const uint32_t* a,
                                       uint32_t b0, uint32_t b1) {
    asm volatile(
        "mma.sync.aligned.m16n8k32.row.col.s32.s8.s8.s32 "
        "{%0,%1,%2,%3}, {%4,%5,%6,%7}, {%8,%9}, {%0,%1,%2,%3};"
        : "+r"(c[0]), "+r"(c[1]), "+r"(c[2]), "+r"(c[3])
        : "r"(a[0]), "r"(a[1]), "r"(a[2]), "r"(a[3]), "r"(b0), "r"(b1));
}

// ---------------- quantize helper ----------------------------------------
__device__ __forceinline__ void quant_split(float f, float inv, int8_t& q1, int8_t& q0) {
    int X = __float2int_rn(f * inv);
    X = max(min(X, 16256), -16256);
    int hi = (X + 64) >> 7;                 // round-to-nearest of X/128
    q1 = (int8_t)hi;
    q0 = (int8_t)(X - (hi << 7));           // in [-64, 64)
}

// ---------------- prep kernels --------------------------------------------
// One CTA (256 threads) per row: row max -> per-row scale -> dual-limb int8.
// act_quant round-trip is exact to fp32 rounding -> skipped entirely.
__global__ void __launch_bounds__(256) prep_x(const float* __restrict__ x,
                                              int8_t* __restrict__ a1,
                                              int8_t* __restrict__ a0,
                                              float* __restrict__ sx) {
    int row = blockIdx.x;
    int t = threadIdx.x;
    const float4* xr = (const float4*)(x + (size_t)row * KK);
    float4 v[4];
    float mx = 0.f;
#pragma unroll
    for (int j = 0; j < 4; j++) {
        v[j] = xr[t + j * 256];
        mx = fmaxf(mx, fmaxf(fmaxf(fabsf(v[j].x), fabsf(v[j].y)),
                             fmaxf(fabsf(v[j].z), fabsf(v[j].w))));
    }
    __shared__ float red[8];
#pragma unroll
    for (int o = 16; o > 0; o >>= 1) mx = fmaxf(mx, __shfl_xor_sync(~0u, mx, o));
    if ((t & 31) == 0) red[t >> 5] = mx;
    __syncthreads();
    mx = red[0];
#pragma unroll
    for (int j = 1; j < 8; j++) mx = fmaxf(mx, red[j]);

    float inv = mx > 0.f ? QMAX / mx : 0.f;
    if (t == 0) sx[row] = mx > 0.f ? mx / QMAX : 0.f;

    char4* o1 = (char4*)(a1 + (size_t)row * KK);
    char4* o0 = (char4*)(a0 + (size_t)row * KK);
#pragma unroll
    for (int j = 0; j < 4; j++) {
        char4 h, l;
        quant_split(v[j].x, inv, h.x, l.x);
        quant_split(v[j].y, inv, h.y, l.y);
        quant_split(v[j].z, inv, h.z, l.z);
        quant_split(v[j].w, inv, h.w, l.w);
        o1[t + j * 256] = h;
        o0[t + j * 256] = l;
    }
}

// Dequant weight (per 128x128 block scale), then row-max + dual-limb int8.
__global__ void __launch_bounds__(256) prep_w(const float* __restrict__ wq,
                                              const float* __restrict__ ws,
                                              int8_t* __restrict__ b1,
                                              int8_t* __restrict__ b0,
                                              float* __restrict__ sw) {
    int row = blockIdx.x;                    // n
    int t = threadIdx.x;
    const float4* wr = (const float4*)(wq + (size_t)row * KK);
    const float* wsr = ws + (row >> 7) * (KK / 128);
    float4 v[4];
    float mx = 0.f;
#pragma unroll
    for (int j = 0; j < 4; j++) {
        int i4 = t + j * 256;                // float4 index; k = i4*4
        float s = wsr[i4 >> 5];              // k/128 = i4/32
        v[j] = wr[i4];
        v[j].x *= s; v[j].y *= s; v[j].z *= s; v[j].w *= s;
        mx = fmaxf(mx, fmaxf(fmaxf(fabsf(v[j].x), fabsf(v[j].y)),
                             fmaxf(fabsf(v[j].z), fabsf(v[j].w))));
    }
    __shared__ float red[8];
#pragma unroll
    for (int o = 16; o > 0; o >>= 1) mx = fmaxf(mx, __shfl_xor_sync(~0u, mx, o));
    if ((t & 31) == 0) red[t >> 5] = mx;
    __syncthreads();
    mx = red[0];
#pragma unroll
    for (int j = 1; j < 8; j++) mx = fmaxf(mx, red[j]);

    float inv = mx > 0.f ? QMAX / mx : 0.f;
    if (t == 0) sw[row] = mx > 0.f ? mx / QMAX : 0.f;

    char4* o1 = (char4*)(b1 + (size_t)row * KK);
    char4* o0 = (char4*)(b0 + (size_t)row * KK);
#pragma unroll
    for (int j = 0; j < 4; j++) {
        char4 h, l;
        quant_split(v[j].x, inv, h.x, l.x);
        quant_split(v[j].y, inv, h.y, l.y);
        quant_split(v[j].z, inv, h.z, l.z);
        quant_split(v[j].w, inv, h.w, l.w);
        o1[t + j * 256] = h;
        o0[t + j * 256] = l;
    }
}

// ---------------- GEMM kernel --------------------------------------------
// CTA 128x128, 256 threads, 8 warps 2(M) x 4(N); warp tile 64x32.
// Dual accumulators: hi = A1*B1 (scale 2^14), cx = A1*B0 + A0*B1 (scale 2^7).
// A0*B0 dropped (~1e-4 relative).

__device__ __forceinline__ void issue_chunk(uint32_t sb, int c, int m0, int n0,
                                            const CUtensorMap* pa1,
                                            const CUtensorMap* pa0,
                                            const CUtensorMap* pb1,
                                            const CUtensorMap* pb0) {
    int st = c % NSTAGE;
    uint32_t mb = sb + 16 * st;
    mbar_expect_tx(mb, (uint32_t)STAGE_BYTES);
    int k0 = c * TILE_K;
    uint32_t base = sb + OFF_TILE + st * STAGE_BYTES;
    tma_load3(base,         pa1, k0, m0, mb);
    tma_load3(base + 16384, pa0, k0, m0, mb);
    tma_load3(base + 32768, pb1, k0, n0, mb);
    tma_load3(base + 49152, pb0, k0, n0, mb);
}

__global__ void __launch_bounds__(256, 1)
gemm_kernel(const __grid_constant__ CUtensorMap map_a1,
            const __grid_constant__ CUtensorMap map_a0,
            const __grid_constant__ CUtensorMap map_b1,
            const __grid_constant__ CUtensorMap map_b0,
            const float* __restrict__ sx,
            const float* __restrict__ sw,
            const float* __restrict__ bias,
            float* __restrict__ out) {
    extern __shared__ char smem[];
    uint32_t sb = smem_u32(smem);
    int tid = threadIdx.x;
    int l = tid & 31, wid = tid >> 5;
    int wm = wid >> 2, wn = wid & 3;        // 2 x 4 warp grid
    int m0 = blockIdx.y * TILE_M;
    int n0 = blockIdx.x * TILE_N;

    if (tid == 0) {
        for (int s = 0; s < NSTAGE; s++) mbar_init(sb + 16 * s, 1);
        asm volatile("fence.proxy.async.shared::cta;" ::: "memory");
    }
    __syncthreads();

    if (tid == 0) {
        issue_chunk(sb, 0, m0, n0, &map_a1, &map_a0, &map_b1, &map_b0);
        issue_chunk(sb, 1, m0, n0, &map_a1, &map_a0, &map_b1, &map_b0);
    }

    // lane constants for swizzled ldmatrix addressing (rows are 128 bytes)
    int lm = l & 15;
    int lh = (l >> 4) << 4;                 // byte-column half: 0 or 16
    uint32_t xorv = (uint32_t)(lm & 7) << 4;
    uint32_t arow[4], brow[2];
#pragma unroll
    for (int mt = 0; mt < 4; mt++) arow[mt] = (uint32_t)(wm * 64 + mt * 16 + lm) * 128;
#pragma unroll
    for (int bt = 0; bt < 2; bt++) brow[bt] = (uint32_t)(wn * 32 + bt * 16 + lm) * 128;

    int acch[4][4][4] = {};
    int accx[4][4][4] = {};

    for (int c = 0; c < NCHUNK; c++) {
        int st = c % NSTAGE;
        uint32_t ph = (uint32_t)((c / NSTAGE) & 1);
        mbar_wait(sb + 16 * st, ph);

        uint32_t sA1 = sb + OFF_TILE + st * STAGE_BYTES;
        uint32_t sA0 = sA1 + 16384, sB1 = sA1 + 32768, sB0 = sA1 + 49152;

#pragma unroll
        for (int ks = 0; ks < TILE_K / 32; ks++) {
            uint32_t lob = ((uint32_t)(lh + ks * 32)) ^ xorv;
            uint32_t a1[4][4], a0[4][4], b1[2][4], b0[2][4];
#pragma unroll
            for (int mt = 0; mt < 4; mt++) ldsm4(a1[mt], sA1 + arow[mt] + lob);
#pragma unroll
            for (int mt = 0; mt < 4; mt++) ldsm4(a0[mt], sA0 + arow[mt] + lob);
#pragma unroll
            for (int bt = 0; bt < 2; bt++) ldsm4(b1[bt], sB1 + brow[bt] + lob);
#pragma unroll
            for (int bt = 0; bt < 2; bt++) ldsm4(b0[bt], sB0 + brow[bt] + lob);

#pragma unroll
            for (int mt = 0; mt < 4; mt++) {
#pragma unroll
                for (int nt = 0; nt < 4; nt++) {
                    int bt = nt >> 1, se = nt & 1;
                    mma_s8(acch[mt][nt], a1[mt], b1[bt][se], b1[bt][se + 2]);
                    mma_s8(accx[mt][nt], a1[mt], b0[bt][se], b0[bt][se + 2]);
                    mma_s8(accx[mt][nt], a0[mt], b1[bt][se], b1[bt][se + 2]);
                }
            }
        }
        __syncthreads();
        if (tid == 0 && c + 2 < NCHUNK) {
            issue_chunk(sb, c + 2, m0, n0, &map_a1, &map_a0, &map_b1, &map_b0);
        }
    }

    // epilogue: y = (hi*2^14 + cx*2^7) * sx[row] * sw[col] + bias[col]
    int g = l >> 2;                // row within m8 group
    int q = (l & 3) * 2;           // col pair within n8
#pragma unroll
    for (int mt = 0; mt < 4; mt++) {
        int r0 = m0 + wm * 64 + mt * 16 + g;
        float sx0 = sx[r0], sx1 = sx[r0 + 8];
#pragma unroll
        for (int nt = 0; nt < 4; nt++) {
            int col = n0 + wn * 32 + nt * 8 + q;
            float2 bv = *reinterpret_cast<const float2*>(bias + col);
            float2 wv = *reinterpret_cast<const float2*>(sw + col);
            float f0 = (float)acch[mt][nt][0] * 16384.f + (float)accx[mt][nt][0] * 128.f;
            float f1 = (float)acch[mt][nt][1] * 16384.f + (float)accx[mt][nt][1] * 128.f;
            float f2 = (float)acch[mt][nt][2] * 16384.f + (float)accx[mt][nt][2] * 128.f;
            float f3 = (float)acch[mt][nt][3] * 16384.f + (float)accx[mt][nt][3] * 128.f;
            float2 v0, v1;
            v0.x = f0 * (sx0 * wv.x) + bv.x;
            v0.y = f1 * (sx0 * wv.y) + bv.y;
            v1.x = f2 * (sx1 * wv.x) + bv.x;
            v1.y = f3 * (sx1 * wv.y) + bv.y;
            *reinterpret_cast<float2*>(out + (size_t)r0 * NN + col) = v0;
            *reinterpret_cast<float2*>(out + (size_t)(r0 + 8) * NN + col) = v1;
        }
    }
}

// ---------------- host launch ---------------------------------------------
typedef CUresult (*PFN_encodeTiled)(CUtensorMap*, CUtensorMapDataType, cuuint32_t,
                                    void*, const cuuint64_t*, const cuuint64_t*,
                                    const cuuint32_t*, const cuuint32_t*,
                                    CUtensorMapInterleave, CUtensorMapSwizzle,
                                    CUtensorMapL2promotion, CUtensorMapFloatOOBfill);

static void encode_map_u8(PFN_encodeTiled enc, CUtensorMap* m, void* ptr,
                          unsigned long long d0, unsigned long long d1,
                          unsigned b0, unsigned b1) {
    cuuint64_t dims[3]    = {d0, d1, 1};
    cuuint64_t strides[2] = {d0, d0 * d1};
    cuuint32_t box[3]     = {b0, b1, 1};
    cuuint32_t es[3]      = {1, 1, 1};
    enc(m, CU_TENSOR_MAP_DATA_TYPE_UINT8, 3, ptr, dims, strides, box, es,
        CU_TENSOR_MAP_INTERLEAVE_NONE, CU_TENSOR_MAP_SWIZZLE_128B,
        CU_TENSOR_MAP_L2_PROMOTION_L2_128B, CU_TENSOR_MAP_FLOAT_OOB_FILL_NONE);
}

extern "C" void kernel_launch(void* const* d_in, const int* in_sizes, int n_in,
                              void* d_out, int out_size) {
    const float* x    = (const float*)d_in[0];
    const float* wq   = (const float*)d_in[1];
    const float* ws   = (const float*)d_in[2];
    const float* bias = (const float*)d_in[3];
    float* out = (float*)d_out;

    void *px1, *px0, *pw1, *pw0, *psx, *psw;
    cudaGetSymbolAddress(&px1, g_x1);
    cudaGetSymbolAddress(&px0, g_x0);
    cudaGetSymbolAddress(&pw1, g_w1);
    cudaGetSymbolAddress(&pw0, g_w0);
    cudaGetSymbolAddress(&psx, g_sx);
    cudaGetSymbolAddress(&psw, g_sw);

    prep_x<<<TT, 256>>>(x, (int8_t*)px1, (int8_t*)px0, (float*)psx);
    prep_w<<<NN, 256>>>(wq, ws, (int8_t*)pw1, (int8_t*)pw0, (float*)psw);

    void* fn = nullptr;
    cudaDriverEntryPointQueryResult qr;
    cudaGetDriverEntryPointByVersion("cuTensorMapEncodeTiled", &fn, 12000,
                                     cudaEnableDefault, &qr);
    PFN_encodeTiled enc = (PFN_encodeTiled)fn;

    CUtensorMap ma1, ma0, mb1, mb0;
    encode_map_u8(enc, &ma1, px1, KK, TT, TILE_K, TILE_M);
    encode_map_u8(enc, &ma0, px0, KK, TT, TILE_K, TILE_M);
    encode_map_u8(enc, &mb1, pw1, KK, NN, TILE_K, TILE_N);
    encode_map_u8(enc, &mb0, pw0, KK, NN, TILE_K, TILE_N);

    cudaFuncSetAttribute(gemm_kernel, cudaFuncAttributeMaxDynamicSharedMemorySize,
                         SMEM_TOTAL);
    dim3 grid(NN / TILE_N, TT / TILE_M);   // 32 x 64
    gemm_kernel<<<grid, 256, SMEM_TOTAL>>>(ma1, ma0, mb1, mb0,
                                           (const float*)psx, (const float*)psw,
                                           bias, out);
}

// round 4
// speedup vs baseline: 7.4892x; 7.4892x over previous
#include <cuda_runtime.h>
#include <cuda.h>
#include <cuda_fp16.h>
#include <cstdint>
#include <cstddef>

// ---------------- problem dims (fixed) ----------------
#define TT 8192
#define KK 4096
#define NN 4096

#define TILE_M 128
#define TILE_N 256
#define TILE_K 64                  // k elements per chunk (128B rows, fp16)
#define NCHUNK (KK / TILE_K)       // 64
#define NSTAGE 4

// stage: A 16KB | B 32KB = 49152
#define STAGE_BYTES 49152
#define OFF_TILE 1024
#define SMEM_TOTAL (OFF_TILE + NSTAGE * STAGE_BYTES)   // 197632

// ---------------- scratch (device globals; no allocation) --------------
__device__ __half g_xh[(size_t)TT * KK];
__device__ __half g_wh[(size_t)NN * KK];

// ---------------- PTX helpers (non-'a' baseline only) -------------------
__device__ __forceinline__ uint32_t smem_u32(const void* p) {
    uint32_t a;
    asm("{ .reg .u64 t; cvta.to.shared.u64 t, %1; cvt.u32.u64 %0, t; }"
        : "=r"(a) : "l"(p));
    return a;
}

__device__ __forceinline__ void mbar_init(uint32_t addr, uint32_t count) {
    asm volatile("mbarrier.init.shared.b64 [%0], %1;" :: "r"(addr), "r"(count) : "memory");
}

__device__ __forceinline__ void mbar_expect_tx(uint32_t addr, uint32_t bytes) {
    asm volatile("mbarrier.arrive.expect_tx.shared.b64 _, [%0], %1;"
                 :: "r"(addr), "r"(bytes) : "memory");
}

__device__ __forceinline__ void mbar_wait(uint32_t addr, uint32_t parity) {
    asm volatile(
        "{\n\t"
        ".reg .pred P;\n\t"
        "LAB_WAIT_%=:\n\t"
        "mbarrier.try_wait.parity.acquire.cta.shared::cta.b64 P, [%0], %1, 0x989680;\n\t"
        "@P bra LAB_DONE_%=;\n\t"
        "bra LAB_WAIT_%=;\n\t"
        "LAB_DONE_%=:\n\t"
        "}"
        :: "r"(addr), "r"(parity) : "memory");
}

__device__ __forceinline__ void tma_load3(uint32_t dst, const CUtensorMap* map,
                                          int cx, int cy, uint32_t mbar) {
    asm volatile(
        "cp.async.bulk.tensor.3d.shared::cta.global.tile.mbarrier::complete_tx::bytes "
        "[%0], [%1, {%2, %3, %4}], [%5];"
        :: "r"(dst), "l"(map), "r"(cx), "r"(cy), "r"(0), "r"(mbar)
        : "memory");
}

__device__ __forceinline__ void ldsm4(uint32_t* r, uint32_t addr) {
    asm volatile("ldmatrix.sync.aligned.m8n8.x4.shared.b16 {%0,%1,%2,%3}, [%4];"
                 : "=r"(r[0]), "=r"(r[1]), "=r"(r[2]), "=r"(r[3]) : "r"(addr));
}

__device__ __forceinline__ void mma_f16(float* c, const uint32_t* a,
                                        uint32_t b0, uint32_t b1) {
    asm volatile(
        "mma.sync.aligned.m16n8k16.row.col.f32.f16.f16.f32 "
        "{%0,%1,%2,%3}, {%4,%5,%6,%7}, {%8,%9}, {%0,%1,%2,%3};"
        : "+f"(c[0]), "+f"(c[1]), "+f"(c[2]), "+f"(c[3])
        : "r"(a[0]), "r"(a[1]), "r"(a[2]), "r"(a[3]), "r"(b0), "r"(b1));
}

// ---------------- prep kernels ------------------------------------------
// act_quant round-trip is exact to fp32 rounding -> skipped; x just converts
// to fp16 (values ~N(0,1): well within fp16 range, no scaling needed).
__global__ void prep_x_kernel(const float4* __restrict__ x,
                              __half2* __restrict__ h, int n4) {
    int i = blockIdx.x * blockDim.x + threadIdx.x;
    if (i >= n4) return;
    float4 v = x[i];
    h[2 * i]     = __floats2half2_rn(v.x, v.y);
    h[2 * i + 1] = __floats2half2_rn(v.z, v.w);
}

// Dequant weight (per 128x128 block scale) then convert to fp16.
__global__ void prep_w_kernel(const float4* __restrict__ wq,
                              const float* __restrict__ ws,
                              __half2* __restrict__ h, int n4) {
    int i = blockIdx.x * blockDim.x + threadIdx.x;
    if (i >= n4) return;
    int e0 = i << 2;                  // element index
    int n = e0 >> 12;                 // / 4096 (K)
    int k = e0 & 4095;
    float s = ws[(n >> 7) * (KK / 128) + (k >> 7)];
    float4 v = wq[i];
    h[2 * i]     = __floats2half2_rn(v.x * s, v.y * s);
    h[2 * i + 1] = __floats2half2_rn(v.z * s, v.w * s);
}

// ---------------- GEMM kernel --------------------------------------------
// CTA 128x256, 256 threads, 8 warps 2(M) x 4(N); warp tile 64x64.
// Single fp16 pass (error budget: ~2.3e-4 vs 1e-3 gate).

__device__ __forceinline__ void issue_chunk(uint32_t sb, int c, int m0, int n0,
                                            const CUtensorMap* pa,
                                            const CUtensorMap* pb) {
    int st = c % NSTAGE;
    uint32_t mb = sb + 16 * st;
    mbar_expect_tx(mb, (uint32_t)STAGE_BYTES);
    int k0 = c * TILE_K;
    uint32_t base = sb + OFF_TILE + st * STAGE_BYTES;
    tma_load3(base,         pa, k0, m0, mb);
    tma_load3(base + 16384, pb, k0, n0, mb);
}

__global__ void __launch_bounds__(256, 1)
gemm_kernel(const __grid_constant__ CUtensorMap map_a,
            const __grid_constant__ CUtensorMap map_b,
            const float* __restrict__ bias,
            float* __restrict__ out) {
    extern __shared__ char smem[];
    uint32_t sb = smem_u32(smem);
    int tid = threadIdx.x;
    int l = tid & 31, wid = tid >> 5;
    int wm = wid >> 2, wn = wid & 3;        // 2 x 4 warp grid
    int m0 = blockIdx.y * TILE_M;
    int n0 = blockIdx.x * TILE_N;

    if (tid == 0) {
        for (int s = 0; s < NSTAGE; s++) mbar_init(sb + 16 * s, 1);
        asm volatile("fence.proxy.async.shared::cta;" ::: "memory");
    }
    __syncthreads();

    if (tid == 0) {
        issue_chunk(sb, 0, m0, n0, &map_a, &map_b);
        issue_chunk(sb, 1, m0, n0, &map_a, &map_b);
        issue_chunk(sb, 2, m0, n0, &map_a, &map_b);
    }

    // lane constants for swizzled ldmatrix addressing (rows are 128 bytes)
    int lm = l & 15;
    int lh = (l >> 4) << 4;                 // byte-column half: 0 or 16
    uint32_t xorv = (uint32_t)(lm & 7) << 4;
    uint32_t arow[4], brow[4];
#pragma unroll
    for (int mt = 0; mt < 4; mt++) arow[mt] = (uint32_t)(wm * 64 + mt * 16 + lm) * 128;
#pragma unroll
    for (int bt = 0; bt < 4; bt++) brow[bt] = (uint32_t)(wn * 64 + bt * 16 + lm) * 128;

    float acc[4][8][4] = {};

    for (int c = 0; c < NCHUNK; c++) {
        int st = c % NSTAGE;
        uint32_t ph = (uint32_t)((c / NSTAGE) & 1);
        mbar_wait(sb + 16 * st, ph);

        uint32_t stA = sb + OFF_TILE + st * STAGE_BYTES;
        uint32_t stB = stA + 16384;

#pragma unroll
        for (int ks = 0; ks < TILE_K / 16; ks++) {
            uint32_t lob = ((uint32_t)(lh + ks * 32)) ^ xorv;
            uint32_t a[4][4], b[4][4];
#pragma unroll
            for (int mt = 0; mt < 4; mt++) ldsm4(a[mt], stA + arow[mt] + lob);
#pragma unroll
            for (int bt = 0; bt < 4; bt++) ldsm4(b[bt], stB + brow[bt] + lob);

#pragma unroll
            for (int mt = 0; mt < 4; mt++) {
#pragma unroll
                for (int nt = 0; nt < 8; nt++) {
                    int bt = nt >> 1, se = nt & 1;
                    mma_f16(acc[mt][nt], a[mt], b[bt][se], b[bt][se + 2]);
                }
            }
        }
        __syncthreads();
        if (tid == 0 && c + 3 < NCHUNK) {
            issue_chunk(sb, c + 3, m0, n0, &map_a, &map_b);
        }
    }

    // epilogue: bias add + fp32 stores (mma C-frag layout)
    int g = l >> 2;                // row within m8 group
    int q = (l & 3) * 2;           // col pair within n8
#pragma unroll
    for (int mt = 0; mt < 4; mt++) {
        int r0 = m0 + wm * 64 + mt * 16 + g;
#pragma unroll
        for (int nt = 0; nt < 8; nt++) {
            int col = n0 + wn * 64 + nt * 8 + q;
            float2 bv = *reinterpret_cast<const float2*>(bias + col);
            float2 v0, v1;
            v0.x = acc[mt][nt][0] + bv.x;
            v0.y = acc[mt][nt][1] + bv.y;
            v1.x = acc[mt][nt][2] + bv.x;
            v1.y = acc[mt][nt][3] + bv.y;
            *reinterpret_cast<float2*>(out + (size_t)r0 * NN + col) = v0;
            *reinterpret_cast<float2*>(out + (size_t)(r0 + 8) * NN + col) = v1;
        }
    }
}

// ---------------- host launch ---------------------------------------------
typedef CUresult (*PFN_encodeTiled)(CUtensorMap*, CUtensorMapDataType, cuuint32_t,
                                    void*, const cuuint64_t*, const cuuint64_t*,
                                    const cuuint32_t*, const cuuint32_t*,
                                    CUtensorMapInterleave, CUtensorMapSwizzle,
                                    CUtensorMapL2promotion, CUtensorMapFloatOOBfill);

static void encode_map(PFN_encodeTiled enc, CUtensorMap* m, void* ptr,
                       unsigned long long d0, unsigned long long d1,
                       unsigned b0, unsigned b1) {
    cuuint64_t dims[3]    = {d0, d1, 1};
    cuuint64_t strides[2] = {d0 * 2ull, d0 * d1 * 2ull};   // fp16
    cuuint32_t box[3]     = {b0, b1, 1};
    cuuint32_t es[3]      = {1, 1, 1};
    enc(m, CU_TENSOR_MAP_DATA_TYPE_FLOAT16, 3, ptr, dims, strides, box, es,
        CU_TENSOR_MAP_INTERLEAVE_NONE, CU_TENSOR_MAP_SWIZZLE_128B,
        CU_TENSOR_MAP_L2_PROMOTION_L2_128B, CU_TENSOR_MAP_FLOAT_OOB_FILL_NONE);
}

extern "C" void kernel_launch(void* const* d_in, const int* in_sizes, int n_in,
                              void* d_out, int out_size) {
    const float* x    = (const float*)d_in[0];
    const float* wq   = (const float*)d_in[1];
    const float* ws   = (const float*)d_in[2];
    const float* bias = (const float*)d_in[3];
    float* out = (float*)d_out;

    void *pxh, *pwh;
    cudaGetSymbolAddress(&pxh, g_xh);
    cudaGetSymbolAddress(&pwh, g_wh);

    int n4x = TT * (KK / 4);
    prep_x_kernel<<<n4x / 256, 256>>>((const float4*)x, (__half2*)pxh, n4x);
    int n4w = NN * (KK / 4);
    prep_w_kernel<<<n4w / 256, 256>>>((const float4*)wq, ws, (__half2*)pwh, n4w);

    void* fn = nullptr;
    cudaDriverEntryPointQueryResult qr;
    cudaGetDriverEntryPointByVersion("cuTensorMapEncodeTiled", &fn, 12000,
                                     cudaEnableDefault, &qr);
    PFN_encodeTiled enc = (PFN_encodeTiled)fn;

    CUtensorMap ma, mb;
    encode_map(enc, &ma, pxh, KK, TT, TILE_K, TILE_M);
    encode_map(enc, &mb, pwh, KK, NN, TILE_K, TILE_N);

    cudaFuncSetAttribute(gemm_kernel, cudaFuncAttributeMaxDynamicSharedMemorySize,
                         SMEM_TOTAL);
    dim3 grid(NN / TILE_N, TT / TILE_M);   // 16 x 64
    gemm_kernel<<<grid, 256, SMEM_TOTAL>>>(ma, mb, bias, out);
}